// round 3
// baseline (speedup 1.0000x reference)
#include <cuda_runtime.h>

// ---------------------------------------------------------------------------
// SSIM (16,3,512,512) fp32, 11x11 gaussian (sigma=1.5), zero padding.
// Separable conv; horizontal pass -> register ring (11 rows) -> vertical pass.
// Round-3: packed fp32x2 math (fma.rn.f32x2 / FFMA2) for the symmetric
// quantity pairs, and interleaved (img1,img2) u64 shared layout so each tap
// is one LDS.64. Cuts per-pixel issue count ~40% (kernel was issue-bound:
// issue=56.7%, fma=40.3%).
// ---------------------------------------------------------------------------

#define IMG_H 512
#define IMG_W 512
#define N_PLANES 48
#define N_BLOCKS (48 * 4 * 4)
#define TOTAL_PIX 12582912.0

#define GW0 0.26601172f
#define GW1 0.21300554f
#define GW2 0.10936069f
#define GW3 0.03600077f
#define GW4 0.00759876f
#define GW5 0.00102842f

__device__ double g_acc;
__device__ unsigned int g_count;

typedef unsigned long long u64;

__device__ __forceinline__ u64 pk2(float lo, float hi) {
    u64 r; asm("mov.b64 %0, {%1, %2};" : "=l"(r) : "f"(lo), "f"(hi)); return r;
}
__device__ __forceinline__ float2 upk2(u64 v) {
    float2 r; asm("mov.b64 {%0, %1}, %2;" : "=f"(r.x), "=f"(r.y) : "l"(v)); return r;
}
__device__ __forceinline__ u64 fma2(u64 a, u64 b, u64 c) {
    u64 d; asm("fma.rn.f32x2 %0, %1, %2, %3;" : "=l"(d) : "l"(a), "l"(b), "l"(c)); return d;
}
__device__ __forceinline__ u64 mul2(u64 a, u64 b) {
    u64 d; asm("mul.rn.f32x2 %0, %1, %2;" : "=l"(d) : "l"(a), "l"(b)); return d;
}

__global__ __launch_bounds__(128)
void ssim_kernel(const float* __restrict__ img1, const float* __restrict__ img2,
                 float* __restrict__ out) {
    const float GWs[11] = {GW5, GW4, GW3, GW2, GW1, GW0, GW1, GW2, GW3, GW4, GW5};
    const int   WI[11]  = {5, 4, 3, 2, 1, 0, 1, 2, 3, 4, 5};

    const int plane = blockIdx.x;
    const int strip = blockIdx.y;
    const int band  = blockIdx.z;
    const int tx    = threadIdx.x;

    const int col0 = strip * 128;
    const int row0 = band * 128;

    const float* __restrict__ p1 = img1 + (size_t)plane * (IMG_H * IMG_W);
    const float* __restrict__ p2 = img2 + (size_t)plane * (IMG_H * IMG_W);

    // interleaved (a,b) pairs: one u64 per column, 139 columns per row
    __shared__ u64 sab[11][139];

    // packed weights in registers (6 distinct)
    u64 W2[6];
    W2[0] = pk2(GW0, GW0); W2[1] = pk2(GW1, GW1); W2[2] = pk2(GW2, GW2);
    W2[3] = pk2(GW3, GW3); W2[4] = pk2(GW4, GW4); W2[5] = pk2(GW5, GW5);
    const u64 NEG1 = pk2(-1.f, -1.f);

    u64   ring01[11];   // (sum w*a, sum w*b)
    u64   ring23[11];   // (sum w*a*a, sum w*b*b)
    float ring4[11];    // sum w*a*b
#pragma unroll
    for (int k = 0; k < 11; ++k) { ring01[k] = 0ull; ring23[k] = 0ull; ring4[k] = 0.f; }

    float acc = 0.f;

    const float C1  = 1e-4f;
    const float C2  = 9e-4f;
    const float C2E = 9e-4f + 1e-6f;

    const int c0 = col0 - 5 + tx;
    const bool colok0 = ((unsigned)c0 < (unsigned)IMG_W);
    const int c1 = c0 + 128;
    const bool colok1 = ((unsigned)c1 < (unsigned)IMG_W);

    for (int t = 0; t < 13; ++t) {
        const int base = row0 - 5 + t * 11;

        __syncthreads();
#pragma unroll
        for (int r = 0; r < 11; ++r) {
            const int y = base + r;
            const bool rowok = ((unsigned)y < (unsigned)IMG_H);
            const float* r1 = p1 + y * IMG_W;
            const float* r2 = p2 + y * IMG_W;
            const bool ok0 = rowok && colok0;
            const float a = ok0 ? __ldg(r1 + c0) : 0.f;
            const float b = ok0 ? __ldg(r2 + c0) : 0.f;
            sab[r][tx] = pk2(a, b);
            if (tx < 11) {
                const bool ok1 = rowok && colok1;
                const float a1 = ok1 ? __ldg(r1 + c1) : 0.f;
                const float b1 = ok1 ? __ldg(r2 + c1) : 0.f;
                sab[r][128 + tx] = pk2(a1, b1);
            }
        }
        __syncthreads();

#pragma unroll
        for (int k = 0; k < 11; ++k) {
            const u64* srow = sab[k];
            u64 h01 = 0ull, h23 = 0ull;
            float h4 = 0.f;
#pragma unroll
            for (int i = 0; i < 11; ++i) {
                const u64 vv = srow[tx + i];          // LDS.64: (a,b)
                const u64 w  = W2[WI[i]];
                h01 = fma2(w, vv, h01);               // (+w*a, +w*b)
                const u64 p = mul2(w, vv);            // (w*a, w*b)
                h23 = fma2(p, vv, h23);               // (+w*a*a, +w*b*b)
                const float2 pf = upk2(p);
                const float2 vf = upk2(vv);
                h4 = fmaf(pf.x, vf.y, h4);            // +w*a*b
            }
            ring01[k] = h01; ring23[k] = h23; ring4[k] = h4;

            const int n = t * 11 + k;
            if (n >= 10 && n < 138) {
                u64 m12 = 0ull, s1122 = 0ull;
                float s12 = 0.f;
#pragma unroll
                for (int j = 0; j < 11; ++j) {
                    const int s = (k + 1 + j) % 11;   // static after unroll
                    const u64 w = W2[WI[j]];
                    m12   = fma2(w, ring01[s], m12);
                    s1122 = fma2(w, ring23[s], s1122);
                    s12   = fmaf(GWs[j], ring4[s], s12);
                }
                const u64 musq = mul2(m12, m12);              // (m1^2, m2^2)
                const u64 sg   = fma2(musq, NEG1, s1122);     // (s11-m1^2, s22-m2^2)
                const float2 mf = upk2(m12);
                const float2 ms = upk2(musq);
                const float2 sf = upk2(sg);
                const float mu12  = mf.x * mf.y;
                const float sig12 = fmaf(-mf.x, mf.y, s12);
                const float v1  = fmaf(2.f, sig12, C2);
                const float v2  = (sf.x + sf.y) + C2E;
                const float num = fmaf(2.f, mu12, C1) * v1;
                const float den = ((ms.x + ms.y) + C1) * v2;
                acc += __fdividef(num, den);
            }
        }
    }

#pragma unroll
    for (int o = 16; o > 0; o >>= 1)
        acc += __shfl_xor_sync(0xFFFFFFFFu, acc, o);

    __shared__ float wsum[4];
    if ((tx & 31) == 0) wsum[tx >> 5] = acc;
    __syncthreads();

    if (tx == 0) {
        const float s = wsum[0] + wsum[1] + wsum[2] + wsum[3];
        atomicAdd(&g_acc, (double)s);
        __threadfence();
        const unsigned int done = atomicAdd(&g_count, 1u);
        if (done == (unsigned)(N_BLOCKS - 1)) {
            const double total = atomicAdd(&g_acc, 0.0);
            out[0] = (float)(total / TOTAL_PIX);
            g_acc = 0.0;
            g_count = 0u;
            __threadfence();
        }
    }
}

extern "C" void kernel_launch(void* const* d_in, const int* in_sizes, int n_in,
                              void* d_out, int out_size) {
    const float* img1 = (const float*)d_in[0];
    const float* img2 = (const float*)d_in[1];
    float* out = (float*)d_out;
    (void)in_sizes; (void)n_in; (void)out_size;

    dim3 grid(N_PLANES, 4, 4);
    ssim_kernel<<<grid, 128>>>(img1, img2, out);
}